// round 15
// baseline (speedup 1.0000x reference)
#include <cuda_runtime.h>

// GRU-ODE: B=32768 rows, T=28, DIM=H=32, 10-step RK4, RHS = 2-layer tanh MLP.
// R9 architecture (4 rows/thread, 8 lanes/group, j-slice 4, f32x2 FMAs) with
// ONE change: the y-exchange buffer is WARP-INTERLEAVED at 16B granularity
// (addr = (r*8+chunk)*16 + group*4 floats), so each y-load instruction's four
// group-addresses land in 64B of a single 128B line -> 1 l1tex wavefront
// instead of 4. Weight loads stay broadcast (1 wf). Targets the calibrated
// wavefront model: ~80 wf/warp/matvec vs R9's ~176.

#define TT 28
#define NSTEPS 10
typedef unsigned long long u64;

struct __align__(16) SW {
    float T1[1024], T2[1024];       // T[k*32+j] = W[j*32+k] (transposed)
    float Tih[3][1024], Thh[3][1024];
    float b1[32], b2[32];
    float br[32], bz[32], bni[32], bnh[32];  // GRU biases (r,z presummed)
};

__device__ __forceinline__ u64 splat2(float x) {
    u64 d; asm("mov.b64 %0, {%1, %1};" : "=l"(d) : "f"(x)); return d;
}
__device__ __forceinline__ float2 unpack2(u64 v) {
    float2 r; asm("mov.b64 {%0, %1}, %2;" : "=f"(r.x), "=f"(r.y) : "l"(v)); return r;
}
__device__ __forceinline__ u64 fma2(u64 a, u64 b, u64 c) {
    u64 d; asm("fma.rn.f32x2 %0, %1, %2, %3;" : "=l"(d) : "l"(a), "l"(b), "l"(c)); return d;
}

__device__ __forceinline__ float sigmoidf_fast(float x) {
    return __fdividef(1.0f, 1.0f + __expf(-x));
}
__device__ __forceinline__ float tanhf_fast(float x) {
    return 1.0f - __fdividef(2.0f, 1.0f + __expf(2.0f * x));
}

// ── warp-interleaved y buffer: 512 floats/warp ──
// slot(r, chunk, g) = (r*8 + chunk)*16 + g*4   (chunk = k/4, g = group 0..3)
__device__ __forceinline__ float* yaddr(float* pb, int g, int r, int c) {
    return pb + (((r << 3) + c) << 4) + (g << 2);
}

// acc[r][p] (f32x2 over j=(ooff+2p,ooff+2p+1)) += y[r][k] * T[k*32+ooff+..],
// r = 0..3 rows. y exchanged via the warp-interleaved buffer.
__device__ __forceinline__ void mv4o(const float* __restrict__ T, int ooff, int g,
                                     float* __restrict__ pb,
                                     const float (&y)[4][4], u64 (&a)[4][2]) {
    const int cb = ooff >> 2;
#pragma unroll
    for (int r = 0; r < 4; ++r)
        *reinterpret_cast<float4*>(yaddr(pb, g, r, cb))
            = make_float4(y[r][0], y[r][1], y[r][2], y[r][3]);
    __syncwarp();
#pragma unroll 1
    for (int src = 0; src < 8; ++src) {          // dynamic: bounds reg hoisting
        const float4 yv0 = *reinterpret_cast<const float4*>(yaddr(pb, g, 0, src));
        const float4 yv1 = *reinterpret_cast<const float4*>(yaddr(pb, g, 1, src));
        const float4 yv2 = *reinterpret_cast<const float4*>(yaddr(pb, g, 2, src));
        const float4 yv3 = *reinterpret_cast<const float4*>(yaddr(pb, g, 3, src));
        const float ym[4][4] = {
            {yv0.x, yv0.y, yv0.z, yv0.w},
            {yv1.x, yv1.y, yv1.z, yv1.w},
            {yv2.x, yv2.y, yv2.z, yv2.w},
            {yv3.x, yv3.y, yv3.z, yv3.w}};
        const int k0 = src * 4;
#pragma unroll
        for (int m = 0; m < 4; ++m) {
            const ulonglong2 w = *reinterpret_cast<const ulonglong2*>(T + (k0 + m) * 32 + ooff);
#pragma unroll
            for (int r = 0; r < 4; ++r) {
                const u64 s = splat2(ym[r][m]);
                a[r][0] = fma2(s, w.x, a[r][0]);
                a[r][1] = fma2(s, w.y, a[r][1]);
            }
        }
    }
    __syncwarp();
}

__device__ __forceinline__ void initacc(const float* __restrict__ b, int ooff,
                                        u64 (&a)[4][2]) {
    const ulonglong2 bb = *reinterpret_cast<const ulonglong2*>(b + ooff);
#pragma unroll
    for (int r = 0; r < 4; ++r) { a[r][0] = bb.x; a[r][1] = bb.y; }
}

// f = tanh(y @ W1^T + b1) @ W2^T + b2 for 4 rows (this thread's 4-j slice).
__device__ __forceinline__ void rhs4(const SW* __restrict__ s, int ooff, int g,
                                     float* __restrict__ pb,
                                     const float (&y)[4][4], float (&f)[4][4]) {
    u64 acc[4][2];
    initacc(s->b1, ooff, acc);
    mv4o(s->T1, ooff, g, pb, y, acc);
    float z[4][4];
#pragma unroll
    for (int r = 0; r < 4; ++r)
#pragma unroll
        for (int p = 0; p < 2; ++p) {
            const float2 v = unpack2(acc[r][p]);
            z[r][2 * p]     = tanhf_fast(v.x);
            z[r][2 * p + 1] = tanhf_fast(v.y);
        }
    initacc(s->b2, ooff, acc);
    mv4o(s->T2, ooff, g, pb, z, acc);
#pragma unroll
    for (int r = 0; r < 4; ++r)
#pragma unroll
        for (int p = 0; p < 2; ++p) {
            const float2 v = unpack2(acc[r][p]);
            f[r][2 * p] = v.x; f[r][2 * p + 1] = v.y;
        }
}

__device__ __forceinline__ void rk4(const SW* __restrict__ s, int ooff, int g,
                                    float* __restrict__ pb,
                                    float (&h)[4][4], float span) {
    const float dt = span * (1.0f / NSTEPS);
#pragma unroll 1
    for (int st = 0; st < NSTEPS; ++st) {
        float yt[4][4], ks[4][4], kc[4][4];
#pragma unroll
        for (int r = 0; r < 4; ++r)
#pragma unroll
            for (int j = 0; j < 4; ++j) { yt[r][j] = h[r][j]; ks[r][j] = 0.0f; }
#pragma unroll 1
        for (int sg = 0; sg < 4; ++sg) {
            rhs4(s, ooff, g, pb, yt, kc);
            const float ws = (sg == 1 || sg == 2) ? 2.0f : 1.0f;
            const float cn = (sg < 2) ? 0.5f * dt : dt;
#pragma unroll
            for (int r = 0; r < 4; ++r)
#pragma unroll
                for (int j = 0; j < 4; ++j) {
                    ks[r][j] = fmaf(ws, kc[r][j], ks[r][j]);
                    yt[r][j] = fmaf(cn, kc[r][j], h[r][j]);  // extra at sg=3: harmless
                }
        }
#pragma unroll
        for (int r = 0; r < 4; ++r)
#pragma unroll
            for (int j = 0; j < 4; ++j)
                h[r][j] = fmaf(dt * (1.0f / 6.0f), ks[r][j], h[r][j]);
    }
}

// PyTorch-order GRU (r,z,n) on 4 rows, 4-j slice.
__device__ __forceinline__ void gru4(const SW* __restrict__ s, int ooff, int g,
                                     float* __restrict__ pb,
                                     float (&h)[4][4], const float (&x)[4][4]) {
    u64 a1[4][2], a2[4][2];
    float rg[4][4], zg[4][4];
    // r gate
    initacc(s->br, ooff, a1);
    mv4o(s->Tih[0], ooff, g, pb, x, a1);
    mv4o(s->Thh[0], ooff, g, pb, h, a1);
#pragma unroll
    for (int r = 0; r < 4; ++r)
#pragma unroll
        for (int p = 0; p < 2; ++p) {
            const float2 v = unpack2(a1[r][p]);
            rg[r][2 * p]     = sigmoidf_fast(v.x);
            rg[r][2 * p + 1] = sigmoidf_fast(v.y);
        }
    // z gate
    initacc(s->bz, ooff, a1);
    mv4o(s->Tih[1], ooff, g, pb, x, a1);
    mv4o(s->Thh[1], ooff, g, pb, h, a1);
#pragma unroll
    for (int r = 0; r < 4; ++r)
#pragma unroll
        for (int p = 0; p < 2; ++p) {
            const float2 v = unpack2(a1[r][p]);
            zg[r][2 * p]     = sigmoidf_fast(v.x);
            zg[r][2 * p + 1] = sigmoidf_fast(v.y);
        }
    // n gate: input part (a1) and hidden part (a2)
    initacc(s->bni, ooff, a1);
    mv4o(s->Tih[2], ooff, g, pb, x, a1);
    initacc(s->bnh, ooff, a2);
    mv4o(s->Thh[2], ooff, g, pb, h, a2);
#pragma unroll
    for (int r = 0; r < 4; ++r)
#pragma unroll
        for (int p = 0; p < 2; ++p) {
            const float2 gi = unpack2(a1[r][p]);
            const float2 gh = unpack2(a2[r][p]);
            const float n0 = tanhf_fast(gi.x + rg[r][2 * p] * gh.x);
            const float n1 = tanhf_fast(gi.y + rg[r][2 * p + 1] * gh.y);
            h[r][2 * p]     = n0 + zg[r][2 * p]     * (h[r][2 * p]     - n0);
            h[r][2 * p + 1] = n1 + zg[r][2 * p + 1] * (h[r][2 * p + 1] - n1);
        }
}

__device__ __forceinline__ void load4(const float* __restrict__ p, float (&v)[4]) {
    const float4 a = *reinterpret_cast<const float4*>(p);
    v[0] = a.x; v[1] = a.y; v[2] = a.z; v[3] = a.w;
}

extern "C" __global__ void __launch_bounds__(128, 3)
ode_gru_kernel(const float* __restrict__ inputs, const float* __restrict__ h0,
               const float* __restrict__ Wih, const float* __restrict__ Whh,
               const float* __restrict__ bih, const float* __restrict__ bhh,
               const float* __restrict__ W1, const float* __restrict__ b1,
               const float* __restrict__ W2, const float* __restrict__ b2,
               float* __restrict__ out, int B) {
    __shared__ SW s;
    __shared__ __align__(16) float ybuf[4 * 512];   // 4 warps x 512 floats

    for (int i = threadIdx.x; i < 1024; i += blockDim.x) {
        const int j = i >> 5, k = i & 31;
        s.T1[k * 32 + j] = W1[i];
        s.T2[k * 32 + j] = W2[i];
    }
    for (int i = threadIdx.x; i < 3072; i += blockDim.x) {
        const int g = i >> 10, r = (i >> 5) & 31, k = i & 31;
        s.Tih[g][k * 32 + r] = Wih[i];
        s.Thh[g][k * 32 + r] = Whh[i];
    }
    for (int i = threadIdx.x; i < 32; i += blockDim.x) {
        s.b1[i]  = b1[i];            s.b2[i]  = b2[i];
        s.br[i]  = bih[i] + bhh[i];  s.bz[i]  = bih[32 + i] + bhh[32 + i];
        s.bni[i] = bih[64 + i];      s.bnh[i] = bhh[64 + i];
    }
    __syncthreads();

    const int gt   = blockIdx.x * blockDim.x + threadIdx.x;
    const int grp4 = gt >> 3;            // 4-row group index (8 lanes each)
    const int ooff = (gt & 7) * 4;       // j-slice offset
    const int row0 = grp4 * 4;
    if (row0 >= B) return;               // grid sized exactly: never taken

    const int g = (threadIdx.x >> 3) & 3;            // group-in-warp
    float* pb = ybuf + (threadIdx.x >> 5) * 512;     // warp buffer

    float h[4][4];
#pragma unroll
    for (int r = 0; r < 4; ++r) load4(h0 + (size_t)(row0 + r) * 32 + ooff, h[r]);

    const float* xb = inputs + (size_t)row0 * TT * 32 + ooff;

    // initial integration over [0, 1]
    rk4(&s, ooff, g, pb, h, 1.0f);

#pragma unroll 1
    for (int t = 0; t < TT; ++t) {
        float x[4][4];
#pragma unroll
        for (int r = 0; r < 4; ++r)
            load4(xb + (size_t)r * TT * 32 + t * 32, x[r]);
        gru4(&s, ooff, g, pb, h, x);
        if (t < TT - 1) rk4(&s, ooff, g, pb, h, 1.0f);
    }

    // h_start -> out[0], then 14-unit integration -> out[1]
#pragma unroll
    for (int r = 0; r < 4; ++r) {
        float4 o = make_float4(fmaxf(h[r][0], 0.0f), fmaxf(h[r][1], 0.0f),
                               fmaxf(h[r][2], 0.0f), fmaxf(h[r][3], 0.0f));
        *reinterpret_cast<float4*>(out + (size_t)(row0 + r) * 32 + ooff) = o;
    }
    rk4(&s, ooff, g, pb, h, 14.0f);
#pragma unroll
    for (int r = 0; r < 4; ++r) {
        float4 o = make_float4(fmaxf(h[r][0], 0.0f), fmaxf(h[r][1], 0.0f),
                               fmaxf(h[r][2], 0.0f), fmaxf(h[r][3], 0.0f));
        *reinterpret_cast<float4*>(out + (size_t)B * 32 + (size_t)(row0 + r) * 32 + ooff) = o;
    }
}

extern "C" void kernel_launch(void* const* d_in, const int* in_sizes, int n_in,
                              void* d_out, int out_size) {
    const float* inputs = (const float*)d_in[0];
    const float* h0     = (const float*)d_in[1];
    const float* Wih    = (const float*)d_in[2];
    const float* Whh    = (const float*)d_in[3];
    const float* bih    = (const float*)d_in[4];
    const float* bhh    = (const float*)d_in[5];
    const float* W1     = (const float*)d_in[6];
    const float* b1     = (const float*)d_in[7];
    const float* W2     = (const float*)d_in[8];
    const float* b2     = (const float*)d_in[9];

    const int B = in_sizes[1] / 32;          // h0 is [B, 32]
    const int threads = 128;
    const long total = ((long)B / 4) * 8;    // 8 threads per 4-row group
    const int blocks = (int)((total + threads - 1) / threads);
    ode_gru_kernel<<<blocks, threads>>>(inputs, h0, Wih, Whh, bih, bhh,
                                        W1, b1, W2, b2, (float*)d_out, B);
}

// round 16
// speedup vs baseline: 1.1360x; 1.1360x over previous
#include <cuda_runtime.h>

// GRU-ODE: B=32768 rows, T=28, DIM=H=32, 10-step RK4, RHS = 2-layer tanh MLP.
// R13 = R9's layout (4 rows/thread, 8 lanes/group, j-slice 4, 65536 threads)
// on R11's packed-state machinery: h/acc/ks are f32x2 u64s; yt and the tanh
// hidden vector are produced directly into the XOR-swizzled smem y-buffer
// (never register-resident). Natural regs ~120 -> launch_bounds(128,4):
// grid 512 fits ONE wave (4 CTAs/SM x 148 = 592), killing R9's 68-CTA tail.

#define TT 28
#define NSTEPS 10
typedef unsigned long long u64;

__device__ __forceinline__ u64 splat2(float x) {
    u64 d; asm("mov.b64 %0, {%1, %1};" : "=l"(d) : "f"(x)); return d;
}
__device__ __forceinline__ u64 pack2(float lo, float hi) {
    u64 d; asm("mov.b64 %0, {%1, %2};" : "=l"(d) : "f"(lo), "f"(hi)); return d;
}
__device__ __forceinline__ float2 unpack2(u64 v) {
    float2 r; asm("mov.b64 {%0, %1}, %2;" : "=f"(r.x), "=f"(r.y) : "l"(v)); return r;
}
__device__ __forceinline__ u64 fma2(u64 a, u64 b, u64 c) {
    u64 d; asm("fma.rn.f32x2 %0, %1, %2, %3;" : "=l"(d) : "l"(a), "l"(b), "l"(c)); return d;
}
__device__ __forceinline__ u64 add2(u64 a, u64 b) {
    u64 d; asm("add.rn.f32x2 %0, %1, %2;" : "=l"(d) : "l"(a), "l"(b)); return d;
}

__device__ __forceinline__ float sigmoidf_fast(float x) {
    return __fdividef(1.0f, 1.0f + __expf(-x));
}
__device__ __forceinline__ float tanhf_fast(float x) {
    return 1.0f - __fdividef(2.0f, 1.0f + __expf(2.0f * x));
}

// ── swizzled group buffer: 256 floats/group, chunk index (row*8 + k/4) ^ grp ──
__device__ __forceinline__ float4 ld4s(const float* __restrict__ gb, int grp, int chunk) {
    return *reinterpret_cast<const float4*>(gb + ((chunk ^ grp) << 2));
}
__device__ __forceinline__ void st4s(float* __restrict__ gb, int grp, int chunk,
                                     u64 a, u64 b) {
    *reinterpret_cast<ulonglong2*>(gb + ((chunk ^ grp) << 2)) = make_ulonglong2(a, b);
}

// acc[r] += y[r] @ T-slice for 4 rows; y read from the swizzled group buffer
// at row base rb (rk4 uses rb=0; GRU x at rb=0, h at rb=4).
__device__ __forceinline__ void mvload4(const float* __restrict__ T, int ooff, int grp,
                                        const float* __restrict__ gb, int rb, u64 (&a)[4][2]) {
#pragma unroll 1
    for (int src = 0; src < 8; ++src) {          // dynamic: bounds reg hoisting
        float ym[4][4];
#pragma unroll
        for (int r = 0; r < 4; ++r) {
            const float4 v = ld4s(gb, grp, (rb + r) * 8 + src);
            ym[r][0] = v.x; ym[r][1] = v.y; ym[r][2] = v.z; ym[r][3] = v.w;
        }
        const int k0 = src * 4;
#pragma unroll
        for (int m = 0; m < 4; ++m) {
            const ulonglong2 w = *reinterpret_cast<const ulonglong2*>(T + (k0 + m) * 32 + ooff);
#pragma unroll
            for (int r = 0; r < 4; ++r) {
                const u64 s = splat2(ym[r][m]);
                a[r][0] = fma2(s, w.x, a[r][0]);
                a[r][1] = fma2(s, w.y, a[r][1]);
            }
        }
    }
}

// One RHS eval for 4 rows: on entry acc = k_prev; stores yt = h + cn*k_prev
// (or h when FIRST), runs tanh-MLP through the buffer, leaves acc = k_new.
template <bool FIRST>
__device__ __forceinline__ void rhs4(const float* __restrict__ T1, const float* __restrict__ T2,
                                     int ooff, int grp, float* __restrict__ gb,
                                     const u64 (&h)[4][2], u64 (&acc)[4][2], u64 cn2,
                                     u64 b1q0, u64 b1q1, u64 b2q0, u64 b2q1) {
    const int cb = ooff >> 2;
#pragma unroll
    for (int r = 0; r < 4; ++r) {
        u64 y0, y1;
        if (FIRST) { y0 = h[r][0]; y1 = h[r][1]; }
        else       { y0 = fma2(cn2, acc[r][0], h[r][0]); y1 = fma2(cn2, acc[r][1], h[r][1]); }
        st4s(gb, grp, r * 8 + cb, y0, y1);
    }
    __syncwarp();
#pragma unroll
    for (int r = 0; r < 4; ++r) { acc[r][0] = b1q0; acc[r][1] = b1q1; }
    mvload4(T1, ooff, grp, gb, 0, acc);
    __syncwarp();
#pragma unroll
    for (int r = 0; r < 4; ++r) {
        const float2 v0 = unpack2(acc[r][0]);
        const float2 v1 = unpack2(acc[r][1]);
        st4s(gb, grp, r * 8 + cb,
             pack2(tanhf_fast(v0.x), tanhf_fast(v0.y)),
             pack2(tanhf_fast(v1.x), tanhf_fast(v1.y)));
    }
    __syncwarp();
#pragma unroll
    for (int r = 0; r < 4; ++r) { acc[r][0] = b2q0; acc[r][1] = b2q1; }
    mvload4(T2, ooff, grp, gb, 0, acc);
    __syncwarp();
}

__device__ __forceinline__ void rk4_4(const float* __restrict__ T1, const float* __restrict__ T2,
                                      int ooff, int grp, float* __restrict__ gb,
                                      u64 (&h)[4][2], float span,
                                      u64 b1q0, u64 b1q1, u64 b2q0, u64 b2q1) {
    const float dt = span * (1.0f / NSTEPS);
    const u64 dth2 = splat2(0.5f * dt);
    const u64 dtf2 = splat2(dt);
    const u64 dt62 = splat2(dt * (1.0f / 6.0f));
    const u64 two2 = splat2(2.0f);
    const u64 one2 = splat2(1.0f);
#pragma unroll 1
    for (int st = 0; st < NSTEPS; ++st) {
        u64 acc[4][2], ks[4][2];
        rhs4<true>(T1, T2, ooff, grp, gb, h, acc, 0ull, b1q0, b1q1, b2q0, b2q1);
#pragma unroll
        for (int r = 0; r < 4; ++r) { ks[r][0] = acc[r][0]; ks[r][1] = acc[r][1]; }
        rhs4<false>(T1, T2, ooff, grp, gb, h, acc, dth2, b1q0, b1q1, b2q0, b2q1);
#pragma unroll
        for (int r = 0; r < 4; ++r) {
            ks[r][0] = fma2(two2, acc[r][0], ks[r][0]);
            ks[r][1] = fma2(two2, acc[r][1], ks[r][1]);
        }
        rhs4<false>(T1, T2, ooff, grp, gb, h, acc, dth2, b1q0, b1q1, b2q0, b2q1);
#pragma unroll
        for (int r = 0; r < 4; ++r) {
            ks[r][0] = fma2(two2, acc[r][0], ks[r][0]);
            ks[r][1] = fma2(two2, acc[r][1], ks[r][1]);
        }
        rhs4<false>(T1, T2, ooff, grp, gb, h, acc, dtf2, b1q0, b1q1, b2q0, b2q1);
#pragma unroll
        for (int r = 0; r < 4; ++r) {
            ks[r][0] = fma2(one2, acc[r][0], ks[r][0]);
            ks[r][1] = fma2(one2, acc[r][1], ks[r][1]);
            h[r][0]  = fma2(dt62, ks[r][0], h[r][0]);
            h[r][1]  = fma2(dt62, ks[r][1], h[r][1]);
        }
    }
}

// PyTorch-order GRU (r,z,n) on 4 rows. x stored to row-slots 0..3, h to 4..7,
// once; then 6 matvecs read them. xg is pre-offset by ooff by the caller.
__device__ __forceinline__ void gru4(const float* __restrict__ Tw, int ooff, int grp,
                                     float* __restrict__ gb, u64 (&h4)[4][2],
                                     const float* __restrict__ xg, int t,
                                     const float* __restrict__ bih,
                                     const float* __restrict__ bhh) {
    const int cb = ooff >> 2;
#pragma unroll
    for (int r = 0; r < 4; ++r) {
        const float4 xv = *reinterpret_cast<const float4*>(xg + (size_t)r * TT * 32 + t * 32);
        st4s(gb, grp, r * 8 + cb, pack2(xv.x, xv.y), pack2(xv.z, xv.w));
        st4s(gb, grp, (4 + r) * 8 + cb, h4[r][0], h4[r][1]);
    }
    __syncwarp();

    const float* Tih = Tw + 2048;
    const float* Thh = Tw + 5120;

    u64 a1[4][2], a2[4][2], rg[4][2], zg[4][2];
    // r gate
    {
        const float4 bi = *reinterpret_cast<const float4*>(bih + ooff);
        const float4 bh = *reinterpret_cast<const float4*>(bhh + ooff);
        const u64 b0 = add2(pack2(bi.x, bi.y), pack2(bh.x, bh.y));
        const u64 b1 = add2(pack2(bi.z, bi.w), pack2(bh.z, bh.w));
#pragma unroll
        for (int r = 0; r < 4; ++r) { a1[r][0] = b0; a1[r][1] = b1; }
    }
    mvload4(Tih + 0 * 1024, ooff, grp, gb, 0, a1);
    mvload4(Thh + 0 * 1024, ooff, grp, gb, 4, a1);
#pragma unroll
    for (int r = 0; r < 4; ++r)
#pragma unroll
        for (int p = 0; p < 2; ++p) {
            const float2 v = unpack2(a1[r][p]);
            rg[r][p] = pack2(sigmoidf_fast(v.x), sigmoidf_fast(v.y));
        }
    // z gate
    {
        const float4 bi = *reinterpret_cast<const float4*>(bih + 32 + ooff);
        const float4 bh = *reinterpret_cast<const float4*>(bhh + 32 + ooff);
        const u64 b0 = add2(pack2(bi.x, bi.y), pack2(bh.x, bh.y));
        const u64 b1 = add2(pack2(bi.z, bi.w), pack2(bh.z, bh.w));
#pragma unroll
        for (int r = 0; r < 4; ++r) { a1[r][0] = b0; a1[r][1] = b1; }
    }
    mvload4(Tih + 1 * 1024, ooff, grp, gb, 0, a1);
    mvload4(Thh + 1 * 1024, ooff, grp, gb, 4, a1);
#pragma unroll
    for (int r = 0; r < 4; ++r)
#pragma unroll
        for (int p = 0; p < 2; ++p) {
            const float2 v = unpack2(a1[r][p]);
            zg[r][p] = pack2(sigmoidf_fast(v.x), sigmoidf_fast(v.y));
        }
    // n gate: input part (a1), hidden part (a2)
    {
        const float4 bi = *reinterpret_cast<const float4*>(bih + 64 + ooff);
        const float4 bh = *reinterpret_cast<const float4*>(bhh + 64 + ooff);
        const u64 i0 = pack2(bi.x, bi.y), i1 = pack2(bi.z, bi.w);
        const u64 h0v = pack2(bh.x, bh.y), h1v = pack2(bh.z, bh.w);
#pragma unroll
        for (int r = 0; r < 4; ++r) {
            a1[r][0] = i0;  a1[r][1] = i1;
            a2[r][0] = h0v; a2[r][1] = h1v;
        }
    }
    mvload4(Tih + 2 * 1024, ooff, grp, gb, 0, a1);
    mvload4(Thh + 2 * 1024, ooff, grp, gb, 4, a2);
#pragma unroll
    for (int r = 0; r < 4; ++r)
#pragma unroll
        for (int p = 0; p < 2; ++p) {
            const float2 gi = unpack2(a1[r][p]);
            const float2 gh = unpack2(a2[r][p]);
            const float2 rr = unpack2(rg[r][p]);
            const float2 zz = unpack2(zg[r][p]);
            const float2 hh = unpack2(h4[r][p]);
            const float n0 = tanhf_fast(gi.x + rr.x * gh.x);
            const float n1 = tanhf_fast(gi.y + rr.y * gh.y);
            h4[r][p] = pack2(n0 + zz.x * (hh.x - n0), n1 + zz.y * (hh.y - n1));
        }
    __syncwarp();
}

extern "C" __global__ void __launch_bounds__(128, 4)
ode_gru_kernel(const float* __restrict__ inputs, const float* __restrict__ h0,
               const float* __restrict__ Wih, const float* __restrict__ Whh,
               const float* __restrict__ bih, const float* __restrict__ bhh,
               const float* __restrict__ W1, const float* __restrict__ b1,
               const float* __restrict__ W2, const float* __restrict__ b2,
               float* __restrict__ out, int B) {
    // Tw layout (floats): [0..1024)=T1, [1024..2048)=T2,
    // [2048..5120)=Tih[3], [5120..8192)=Thh[3]; transposed T[k*32+j]=W[j*32+k].
    __shared__ __align__(16) float Tw[8192];
    __shared__ __align__(16) float ybuf[16 * 256];

    for (int i = threadIdx.x; i < 1024; i += blockDim.x) {
        const int j = i >> 5, k = i & 31;
        Tw[k * 32 + j]        = W1[i];
        Tw[1024 + k * 32 + j] = W2[i];
    }
    for (int i = threadIdx.x; i < 3072; i += blockDim.x) {
        const int g = i >> 10, r = (i >> 5) & 31, k = i & 31;
        Tw[2048 + g * 1024 + k * 32 + r] = Wih[i];
        Tw[5120 + g * 1024 + k * 32 + r] = Whh[i];
    }
    __syncthreads();

    const int gt   = blockIdx.x * blockDim.x + threadIdx.x;
    const int grp4 = gt >> 3;            // 4-row group index (8 lanes each)
    const int ooff = (gt & 7) * 4;       // j-slice offset
    const int row0 = grp4 * 4;
    if (row0 >= B) return;               // grid sized exactly: never taken

    const int grp = (threadIdx.x >> 3) & 3;          // swizzle key within warp
    float* gb = ybuf + (threadIdx.x >> 3) * 256;     // per-group buffer

    // MLP biases in registers
    u64 b1q0, b1q1, b2q0, b2q1;
    {
        const float4 v1 = *reinterpret_cast<const float4*>(b1 + ooff);
        const float4 v2 = *reinterpret_cast<const float4*>(b2 + ooff);
        b1q0 = pack2(v1.x, v1.y); b1q1 = pack2(v1.z, v1.w);
        b2q0 = pack2(v2.x, v2.y); b2q1 = pack2(v2.z, v2.w);
    }

    u64 h[4][2];
#pragma unroll
    for (int r = 0; r < 4; ++r) {
        const float4 v = *reinterpret_cast<const float4*>(h0 + (size_t)(row0 + r) * 32 + ooff);
        h[r][0] = pack2(v.x, v.y); h[r][1] = pack2(v.z, v.w);
    }

    const float* xg = inputs + (size_t)row0 * TT * 32 + ooff;  // rows 0..3, pre-offset

    // initial integration over [0, 1]
    rk4_4(Tw, Tw + 1024, ooff, grp, gb, h, 1.0f, b1q0, b1q1, b2q0, b2q1);

#pragma unroll 1
    for (int t = 0; t < TT; ++t) {
        gru4(Tw, ooff, grp, gb, h, xg, t, bih, bhh);
        if (t < TT - 1)
            rk4_4(Tw, Tw + 1024, ooff, grp, gb, h, 1.0f, b1q0, b1q1, b2q0, b2q1);
    }

    // h_start -> out[0], then 14-unit integration -> out[1]
#pragma unroll
    for (int r = 0; r < 4; ++r) {
        const float2 v0 = unpack2(h[r][0]);
        const float2 v1 = unpack2(h[r][1]);
        *reinterpret_cast<float4*>(out + (size_t)(row0 + r) * 32 + ooff) =
            make_float4(fmaxf(v0.x, 0.0f), fmaxf(v0.y, 0.0f),
                        fmaxf(v1.x, 0.0f), fmaxf(v1.y, 0.0f));
    }
    rk4_4(Tw, Tw + 1024, ooff, grp, gb, h, 14.0f, b1q0, b1q1, b2q0, b2q1);
#pragma unroll
    for (int r = 0; r < 4; ++r) {
        const float2 v0 = unpack2(h[r][0]);
        const float2 v1 = unpack2(h[r][1]);
        *reinterpret_cast<float4*>(out + (size_t)B * 32 + (size_t)(row0 + r) * 32 + ooff) =
            make_float4(fmaxf(v0.x, 0.0f), fmaxf(v0.y, 0.0f),
                        fmaxf(v1.x, 0.0f), fmaxf(v1.y, 0.0f));
    }
}

extern "C" void kernel_launch(void* const* d_in, const int* in_sizes, int n_in,
                              void* d_out, int out_size) {
    const float* inputs = (const float*)d_in[0];
    const float* h0     = (const float*)d_in[1];
    const float* Wih    = (const float*)d_in[2];
    const float* Whh    = (const float*)d_in[3];
    const float* bih    = (const float*)d_in[4];
    const float* bhh    = (const float*)d_in[5];
    const float* W1     = (const float*)d_in[6];
    const float* b1     = (const float*)d_in[7];
    const float* W2     = (const float*)d_in[8];
    const float* b2     = (const float*)d_in[9];

    const int B = in_sizes[1] / 32;          // h0 is [B, 32]
    const int threads = 128;
    const long total = ((long)B / 4) * 8;    // 8 threads per 4-row group = 65536
    const int blocks = (int)((total + threads - 1) / threads);
    ode_gru_kernel<<<blocks, threads>>>(inputs, h0, Wih, Whh, bih, bhh,
                                        W1, b1, W2, b2, (float*)d_out, B);
}